// round 8
// baseline (speedup 1.0000x reference)
#include <cuda_runtime.h>
#include <cstdint>

// Problem constants
#define BB   16
#define CC   256
#define SS   512
#define IMG  4096   // 64*64

// ---------------- device scratch (static, no runtime alloc) ----------------
__device__ float g_style1[BB*CC];
__device__ float g_style2[BB*CC];
__device__ float g_demod1[BB*CC];
__device__ float g_demod2[BB*CC];
__device__ float g_wT1[2304*256];      // [ci*9+t][co]
__device__ float g_wT2[2304*256];
__device__ float g_xmod[BB*CC*IMG];    // 67 MB
__device__ float g_hmod[BB*CC*IMG];    // 67 MB

// ---------------- f32x2 helpers ----------------
__device__ __forceinline__ unsigned long long pack2(float lo, float hi) {
    unsigned long long r;
    asm("mov.b64 %0, {%1, %2};" : "=l"(r) : "f"(lo), "f"(hi));
    return r;
}
__device__ __forceinline__ void unpack2(unsigned long long v, float& lo, float& hi) {
    asm("mov.b64 {%0, %1}, %2;" : "=f"(lo), "=f"(hi) : "l"(v));
}
__device__ __forceinline__ void ffma2(unsigned long long& d, unsigned long long a,
                                      unsigned long long b) {
    asm("fma.rn.f32x2 %0, %1, %2, %0;" : "+l"(d) : "l"(a), "l"(b));
}

// ---------------- style = (w * scale) @ s_w^T + s_b ----------------
// scale = 2^-0.5 * 512^-0.5 = 1/32
template<int L>
__global__ void style_kernel(const float* __restrict__ wv,   // [16][512]
                             const float* __restrict__ sw,   // [256][512]
                             const float* __restrict__ sb) { // [256]
    const int b = blockIdx.x;
    const int c = threadIdx.x;             // 256 threads
    __shared__ float sv[512];
    sv[c]       = wv[b*512 + c];
    sv[c + 256] = wv[b*512 + 256 + c];
    __syncthreads();

    float acc = 0.f;
    const float4* row = (const float4*)(sw + (size_t)c*512);
#pragma unroll 8
    for (int q = 0; q < 128; ++q) {
        float4 w4 = row[q];
        acc += w4.x*sv[4*q] + w4.y*sv[4*q+1] + w4.z*sv[4*q+2] + w4.w*sv[4*q+3];
    }
    float* st = (L == 0) ? g_style1 : g_style2;
    st[b*256 + c] = acc * 0.03125f + sb[c];
}

// ---------------- weight transpose: [co][ci][t] -> [ci*9+t][co] ----------------
template<int L>
__global__ void transpose_w_kernel(const float* __restrict__ w) {
    int i = blockIdx.x * 256 + threadIdx.x;   // grid 2304 -> 589824 elements
    int row = i >> 8;                          // ci*9+t
    int co  = i & 255;
    int ci  = row / 9;
    int t   = row - ci * 9;
    float* wt = (L == 0) ? g_wT1 : g_wT2;
    wt[i] = w[(size_t)co*2304 + ci*9 + t];
}

// ---------------- demod[b][co] = rsqrt( sum_{ci,t} (w*style)^2 + eps ) --------
template<int L>
__global__ void demod_kernel() {
    const float* style = (L == 0) ? g_style1 : g_style2;
    const float* wT    = (L == 0) ? g_wT1    : g_wT2;
    float*       dm    = (L == 0) ? g_demod1 : g_demod2;
    const int b  = blockIdx.x;
    const int co = threadIdx.x;
    __shared__ float s2[256];
    float sv = style[b*256 + threadIdx.x];
    s2[threadIdx.x] = sv * sv;
    __syncthreads();

    float acc = 0.f;
    for (int ci = 0; ci < 256; ++ci) {
        float st = s2[ci];
        const float* wrow = wT + (size_t)(ci*9)*256 + co;
        float part = 0.f;
#pragma unroll
        for (int t = 0; t < 9; ++t) { float v = wrow[t*256]; part += v*v; }
        acc += part * st;
    }
    dm[b*256 + co] = rsqrtf(acc + 1e-8f);
}

// ---------------- xmod = x * style1[b][ci] ----------------
__global__ void modulate_kernel(const float* __restrict__ x) {
    size_t i = (size_t)blockIdx.x * 256 + threadIdx.x;  // over 4194304 float4s
    float4 v = ((const float4*)x)[i];
    float  s = g_style1[(int)(i >> 10)];                // 1024 float4 / channel
    v.x *= s; v.y *= s; v.z *= s; v.w *= s;
    ((float4*)g_xmod)[i] = v;
}

// ---------------- fused modulated conv 3x3 + noise + lrelu (+ next-layer style) --
// Block: 64 cout x 16x16 px for one image. Thread: 8 co (4 f32x2 pairs) x 8 px.
template<int LAYER>
__global__ void __launch_bounds__(256, 1)
conv_kernel(const float* __restrict__ noise,   // [16][64][64]
            const float* __restrict__ nw,      // [256]
            float* __restrict__ out_ext) {
    const float* __restrict__ in   = (LAYER == 0) ? g_xmod  : g_hmod;
    const float* __restrict__ wT   = (LAYER == 0) ? g_wT1   : g_wT2;
    const float* __restrict__ dmod = (LAYER == 0) ? g_demod1 : g_demod2;

    const int sp  = blockIdx.x;          // 0..15 spatial tile
    const int co0 = blockIdx.y << 6;     // 0,64,128,192
    const int b   = blockIdx.z;          // 0..15

    const int ty0 = (sp >> 2) << 4;
    const int tx0 = (sp & 3) << 4;

    const int tid  = threadIdx.x;
    const int cog  = tid & 7;            // co group: co_local = cog*8 + [0,8)
    const int pg   = tid >> 3;           // 0..31
    const int prow = pg >> 1;            // 0..15
    const int pcol = (pg & 1) << 3;      // 0 or 8

    __shared__ __align__(16) float sIn[8][18][18];   // ci-chunk x (16+2)^2 halo
    __shared__ __align__(16) float sW[8 * 9 * 64];   // [ci][tap][co_local]

    unsigned long long acc[4][8];
#pragma unroll
    for (int p = 0; p < 4; ++p)
#pragma unroll
        for (int m = 0; m < 8; ++m) acc[p][m] = 0ULL;

    const float* inB = in + (size_t)b * CC * IMG;

    for (int ck = 0; ck < 32; ++ck) {
        const int ci0 = ck << 3;
        __syncthreads();
        // input tile with halo (zero pad at image borders)
        for (int i = tid; i < 8*18*18; i += 256) {
            int ci = i / 324;
            int r  = i - ci * 324;
            int yy = r / 18;
            int xx = r - yy * 18;
            int gy = ty0 - 1 + yy;
            int gx = tx0 - 1 + xx;
            float v = 0.f;
            if ((unsigned)gy < 64u && (unsigned)gx < 64u)
                v = inB[(size_t)(ci0 + ci) * IMG + gy * 64 + gx];
            sIn[ci][yy][xx] = v;
        }
        // weights for this ci-chunk, co tile (coalesced: wT is [ci*9+t][co])
        for (int i = tid; i < 8*9*64; i += 256) {
            sW[i] = wT[(size_t)(ci0 * 9 + (i >> 6)) * 256 + co0 + (i & 63)];
        }
        __syncthreads();

#pragma unroll 1
        for (int ci = 0; ci < 8; ++ci) {
#pragma unroll
            for (int dy = 0; dy < 3; ++dy) {
                // sliding 10-wide row of activations, duplicated into both f32x2 halves
                unsigned long long x2[10];
#pragma unroll
                for (int k = 0; k < 10; ++k) {
                    float xv = sIn[ci][prow + dy][pcol + k];
                    x2[k] = pack2(xv, xv);
                }
#pragma unroll
                for (int dx = 0; dx < 3; ++dx) {
                    const unsigned long long* wp =
                        (const unsigned long long*)&sW[(ci*9 + dy*3 + dx)*64 + cog*8];
                    unsigned long long w0 = wp[0], w1 = wp[1], w2 = wp[2], w3 = wp[3];
#pragma unroll
                    for (int m = 0; m < 8; ++m) {
                        unsigned long long xv = x2[m + dx];
                        ffma2(acc[0][m], w0, xv);
                        ffma2(acc[1][m], w1, xv);
                        ffma2(acc[2][m], w2, xv);
                        ffma2(acc[3][m], w3, xv);
                    }
                }
            }
        }
    }

    // ---------------- epilogue ----------------
    float nz[8];
    {
        const float4* np = (const float4*)(noise + (size_t)b*IMG + (ty0+prow)*64 + tx0 + pcol);
        float4 a0 = np[0], a1 = np[1];
        nz[0]=a0.x; nz[1]=a0.y; nz[2]=a0.z; nz[3]=a0.w;
        nz[4]=a1.x; nz[5]=a1.y; nz[6]=a1.z; nz[7]=a1.w;
    }
    float* outbase = (LAYER == 0) ? g_hmod : out_ext;

#pragma unroll
    for (int p = 0; p < 4; ++p) {
        float lo[8], hi[8];
#pragma unroll
        for (int m = 0; m < 8; ++m) unpack2(acc[p][m], lo[m], hi[m]);
#pragma unroll
        for (int u = 0; u < 2; ++u) {
            const int co = co0 + cog*8 + 2*p + u;
            const float d = dmod[b*256 + co];
            const float w = nw[co];
            const float s = (LAYER == 0) ? g_style2[b*256 + co] : 1.f;
            float vals[8];
#pragma unroll
            for (int m = 0; m < 8; ++m) {
                float a = (u == 0) ? lo[m] : hi[m];
                float v = d * a + w * nz[m];
                v = (v > 0.f) ? v : 0.2f * v;
                vals[m] = v * s;
            }
            float4* op = (float4*)(outbase + (size_t)(b*256 + co)*IMG
                                   + (ty0 + prow)*64 + tx0 + pcol);
            op[0] = make_float4(vals[0], vals[1], vals[2], vals[3]);
            op[1] = make_float4(vals[4], vals[5], vals[6], vals[7]);
        }
    }
}

// ---------------- launch ----------------
extern "C" void kernel_launch(void* const* d_in, const int* in_sizes, int n_in,
                              void* d_out, int out_size) {
    const float* x       = (const float*)d_in[0];
    const float* w1      = (const float*)d_in[1];
    const float* w2      = (const float*)d_in[2];
    const float* noise1  = (const float*)d_in[3];
    const float* noise2  = (const float*)d_in[4];
    const float* s1_w    = (const float*)d_in[5];
    const float* s1_b    = (const float*)d_in[6];
    const float* conv1_w = (const float*)d_in[7];
    const float* nw1     = (const float*)d_in[8];
    const float* s2_w    = (const float*)d_in[9];
    const float* s2_b    = (const float*)d_in[10];
    const float* conv2_w = (const float*)d_in[11];
    const float* nw2     = (const float*)d_in[12];
    float* out = (float*)d_out;

    style_kernel<0><<<16, 256>>>(w1, s1_w, s1_b);
    style_kernel<1><<<16, 256>>>(w2, s2_w, s2_b);
    transpose_w_kernel<0><<<2304, 256>>>(conv1_w);
    transpose_w_kernel<1><<<2304, 256>>>(conv2_w);
    demod_kernel<0><<<16, 256>>>();
    demod_kernel<1><<<16, 256>>>();
    modulate_kernel<<<16384, 256>>>(x);

    dim3 grid(16, 4, 16);   // spatial tiles, co tiles, batch
    conv_kernel<0><<<grid, 256>>>(noise1, nw1, nullptr);
    conv_kernel<1><<<grid, 256>>>(noise2, nw2, out);
}

// round 12
// speedup vs baseline: 1.7025x; 1.7025x over previous
#include <cuda_runtime.h>
#include <cuda_bf16.h>
#include <cstdint>

#define BB   16
#define CC   256
#define IMG  4096
#define KTOT 2304

// ---------------- device scratch ----------------
__device__ float g_style1[BB*CC], g_style2[BB*CC];
__device__ float g_demod1[BB*CC], g_demod2[BB*CC];
__device__ float g_wsq1[CC*CC],  g_wsq2[CC*CC];           // [ci][co] sum_t w^2
__device__ __nv_bfloat16 g_w1h[CC*KTOT], g_w1l[CC*KTOT];  // [co][tap*256+ci]
__device__ __nv_bfloat16 g_w2h[CC*KTOT], g_w2l[CC*KTOT];
__device__ __nv_bfloat16 g_xh[(size_t)BB*IMG*CC], g_xl[(size_t)BB*IMG*CC]; // [b][px][ci]
__device__ __nv_bfloat16 g_hh[(size_t)BB*IMG*CC], g_hl[(size_t)BB*IMG*CC];

// ---------------- helpers ----------------
__device__ __forceinline__ uint32_t smem_u32(const void* p) {
    uint32_t a;
    asm("{ .reg .u64 t; cvta.to.shared.u64 t, %1; cvt.u32.u64 %0, t; }" : "=r"(a) : "l"(p));
    return a;
}
__device__ __forceinline__ void cp16(uint32_t dst, const void* src) {
    asm volatile("cp.async.ca.shared.global [%0], [%1], 16;" :: "r"(dst), "l"(src) : "memory");
}
__device__ __forceinline__ void cp16z(uint32_t dst, const void* src, uint32_t sz) {
    asm volatile("cp.async.ca.shared.global [%0], [%1], 16, %2;" :: "r"(dst), "l"(src), "r"(sz) : "memory");
}
#define CP_WAIT_ALL() asm volatile("cp.async.wait_all;" ::: "memory")

#define LDSM4(r, a) \
    asm volatile("ldmatrix.sync.aligned.m8n8.x4.shared.b16 {%0,%1,%2,%3}, [%4];" \
        : "=r"((r)[0]), "=r"((r)[1]), "=r"((r)[2]), "=r"((r)[3]) : "r"(a))

#define MMA16816(c, a, b0, b1) \
    asm volatile("mma.sync.aligned.m16n8k16.row.col.f32.bf16.bf16.f32 " \
        "{%0,%1,%2,%3},{%4,%5,%6,%7},{%8,%9},{%0,%1,%2,%3};" \
        : "+f"((c)[0]), "+f"((c)[1]), "+f"((c)[2]), "+f"((c)[3]) \
        : "r"((a)[0]), "r"((a)[1]), "r"((a)[2]), "r"((a)[3]), "r"(b0), "r"(b1))

// ---------------- style = (w/32) @ s_w^T + s_b ----------------
template<int L>
__global__ void style_kernel(const float* __restrict__ wv, const float* __restrict__ sw,
                             const float* __restrict__ sb) {
    const int b = blockIdx.x, c = threadIdx.x;
    __shared__ float sv[512];
    sv[c] = wv[b*512 + c]; sv[c+256] = wv[b*512 + 256 + c];
    __syncthreads();
    float acc = 0.f;
    const float4* row = (const float4*)(sw + (size_t)c*512);
#pragma unroll 8
    for (int q = 0; q < 128; ++q) {
        float4 w4 = row[q];
        acc += w4.x*sv[4*q] + w4.y*sv[4*q+1] + w4.z*sv[4*q+2] + w4.w*sv[4*q+3];
    }
    (L == 0 ? g_style1 : g_style2)[b*256 + c] = acc * 0.03125f + sb[c];
}

// ---------------- wsq[ci][co] = sum_t w[co][ci][t]^2 ----------------
template<int L>
__global__ void wsq_kernel(const float* __restrict__ w) {
    int co = blockIdx.x, ci = threadIdx.x;
    const float* p = w + (size_t)co*KTOT + ci*9;
    float a = 0.f;
#pragma unroll
    for (int t = 0; t < 9; ++t) a += p[t]*p[t];
    (L == 0 ? g_wsq1 : g_wsq2)[ci*256 + co] = a;
}

// ---------------- demod ----------------
template<int L>
__global__ void demod_kernel() {
    const float* style = (L == 0) ? g_style1 : g_style2;
    const float* wsq   = (L == 0) ? g_wsq1   : g_wsq2;
    float*       dm    = (L == 0) ? g_demod1 : g_demod2;
    const int b = blockIdx.x, co = threadIdx.x;
    __shared__ float s2[256];
    float sv = style[b*256 + co];
    s2[co] = sv*sv;
    __syncthreads();
    float acc = 0.f;
    for (int ci = 0; ci < 256; ++ci) acc += s2[ci] * wsq[ci*256 + co];
    dm[b*256 + co] = rsqrtf(acc + 1e-8f);
}

// ---------------- weight convert: [co][ci*9+tap] -> bf16 hi/lo [co][tap*256+ci] ----
template<int L>
__global__ void wcv_kernel(const float* __restrict__ w) {
    int i = blockIdx.x*256 + threadIdx.x;
    int co = i / KTOT;
    int r  = i - co*KTOT;
    int tap = r >> 8, ci = r & 255;
    float v = w[(size_t)co*KTOT + ci*9 + tap];
    __nv_bfloat16 h = __float2bfloat16(v);
    (L == 0 ? g_w1h : g_w2h)[i] = h;
    (L == 0 ? g_w1l : g_w2l)[i] = __float2bfloat16(v - __bfloat162float(h));
}

// ---------------- x transpose + modulate + bf16 split -> [b][px][ci] ----------------
__global__ void xt_kernel(const float* __restrict__ x) {
    __shared__ float s[64][65];
    const int px0 = blockIdx.x << 6, ci0 = blockIdx.y << 6, b = blockIdx.z;
    const int t = threadIdx.x;
    for (int i = t; i < 1024; i += 256) {
        int ci = i >> 4, q = i & 15;
        float4 v = ((const float4*)(x + (size_t)(b*CC + ci0 + ci)*IMG + px0))[q];
        float st = g_style1[b*CC + ci0 + ci];
        s[ci][q*4+0] = v.x*st; s[ci][q*4+1] = v.y*st;
        s[ci][q*4+2] = v.z*st; s[ci][q*4+3] = v.w*st;
    }
    __syncthreads();
    const int px_l = t >> 2, seg = t & 3;
    __align__(16) __nv_bfloat16 hb[16], lb[16];
#pragma unroll
    for (int k = 0; k < 16; ++k) {
        float v = s[seg*16 + k][px_l];
        __nv_bfloat16 h = __float2bfloat16(v);
        hb[k] = h;
        lb[k] = __float2bfloat16(v - __bfloat162float(h));
    }
    size_t o = (size_t)(b*IMG + px0 + px_l)*256 + ci0 + seg*16;
    ((uint4*)(g_xh + o))[0] = ((const uint4*)hb)[0];
    ((uint4*)(g_xh + o))[1] = ((const uint4*)hb)[1];
    ((uint4*)(g_xl + o))[0] = ((const uint4*)lb)[0];
    ((uint4*)(g_xl + o))[1] = ((const uint4*)lb)[1];
}

// ================= HMMA implicit-GEMM conv3x3 + fused epilogue =================
// CTA: 128 co x 128 px, 8 warps (2 co-groups x 4 px-groups), warp tile 64x32.
// smem: [0,128)        zero row
//       [1024 +32K*ab) A stage: Ah 16K | Al 16K   (ab = it&1)
//       [66560+66K*bb) B halo : Bh 33792 | Bl 33792 (258 rows x 128B, bb = chunk&1)
#define A_OFF   1024
#define A_STG   32768
#define B_OFF   66560
#define B_STG   67584
#define B_LO    33792
#define SMEM_TOTAL (B_OFF + 2*B_STG)   // 201728

template<int LAYER>
__global__ void __launch_bounds__(256, 1)
conv_hmma(const float* __restrict__ noise, const float* __restrict__ nw,
          float* __restrict__ out) {
    extern __shared__ __align__(1024) char smem[];
    const uint32_t sb32 = smem_u32(smem);
    const int tid = threadIdx.x;
    const int lid = tid & 31, wid = tid >> 5;
    const int wco = wid & 1, wpx = wid >> 1;

    const int px0 = blockIdx.x << 7;
    const int co0 = blockIdx.y << 7;
    const int b   = blockIdx.z;

    const __nv_bfloat16* __restrict__ Bhp = (LAYER == 0) ? g_xh  : g_hh;
    const __nv_bfloat16* __restrict__ Blp = (LAYER == 0) ? g_xl  : g_hl;
    const __nv_bfloat16* __restrict__ Whp = (LAYER == 0) ? g_w1h : g_w2h;
    const __nv_bfloat16* __restrict__ Wlp = (LAYER == 0) ? g_w1l : g_w2l;
    const float* __restrict__ dmod = (LAYER == 0) ? g_demod1 : g_demod2;

    // zero row for invalid B lanes
    if (tid < 8) ((uint4*)smem)[tid] = make_uint4(0, 0, 0, 0);

    // ---- loaders ----
    auto loadA = [&](int it2) {
        const int ntap = it2 % 9, nci = (it2 / 9) << 6;
        const int co_l = tid >> 1, half = tid & 1;
        const size_t gs = (size_t)(co0 + co_l)*KTOT + ntap*256 + nci + half*32;
        const __nv_bfloat16* sh = Whp + gs;
        const __nv_bfloat16* sl = Wlp + gs;
        uint32_t d0 = sb32 + A_OFF + (it2 & 1)*A_STG
                    + co_l*128 + (((co_l & 7) << 4) ^ (half << 6));
#pragma unroll
        for (int j = 0; j < 4; ++j) {
            cp16(d0 ^ (j << 4),              sh + j*8);
            cp16((d0 + 16384) ^ (j << 4),    sl + j*8);
        }
    };
    auto loadB = [&](int chunk) {
        const uint32_t bb = sb32 + B_OFF + (chunk & 1)*B_STG;
        const int nci = chunk << 6;
        const int half = tid & 1;
        for (int r = tid >> 1; r < 258; r += 128) {
            int pp = px0 - 65 + r;
            bool ok = (pp >= 0) && (pp < IMG);
            int ppc = ok ? pp : 0;
            const size_t gs = ((size_t)(b*IMG + ppc))*256 + nci + half*32;
            const __nv_bfloat16* sh = Bhp + gs;
            const __nv_bfloat16* sl = Blp + gs;
            uint32_t sz = ok ? 16u : 0u;
            uint32_t d0 = bb + r*128 + (((r & 7) << 4) ^ (half << 6));
#pragma unroll
            for (int j = 0; j < 4; ++j) {
                cp16z(d0 ^ (j << 4),            sh + j*8, sz);
                cp16z((d0 + B_LO) ^ (j << 4),   sl + j*8, sz);
            }
        }
    };

    loadB(0);
    loadA(0);

    float c[4][4][4];
#pragma unroll
    for (int i = 0; i < 4; ++i)
#pragma unroll
        for (int j = 0; j < 4; ++j)
#pragma unroll
            for (int q = 0; q < 4; ++q) c[i][j][q] = 0.f;

    const int lrow = lid & 15;
    const uint32_t lhi = (uint32_t)((lid >> 4) << 4);

    for (int it = 0; it < 36; ++it) {
        CP_WAIT_ALL();
        __syncthreads();
        if (it + 1 < 36) {
            loadA(it + 1);
            if (((it + 1) % 9) == 0) loadB((it + 1) / 9);
        }

        const int chunk = it / 9;
        const int tap   = it - chunk*9;
        const int dy    = tap / 3 - 1;
        const int dx    = tap - (tap / 3)*3 - 1;
        const uint32_t abuf = sb32 + A_OFF + (it & 1)*A_STG;
        const uint32_t bbuf = sb32 + B_OFF + (chunk & 1)*B_STG;

        uint32_t aH[4], aL[4];
#pragma unroll
        for (int i = 0; i < 4; ++i) {
            int ar = wco*64 + i*16 + lrow;
            aH[i] = abuf + ar*128 + ((((uint32_t)ar & 7) << 4) ^ lhi);
            aL[i] = aH[i] + 16384;
        }
        uint32_t bH[2], bL[2];
#pragma unroll
        for (int g = 0; g < 2; ++g) {
            int pr = wpx*32 + g*16 + lrow;
            int x  = pr & 63;
            int pp = px0 + pr + dy*64 + dx;
            bool ok = !((x == 0 && dx < 0) || (x == 63 && dx > 0))
                      && (pp >= 0) && (pp < IMG);
            if (ok) {
                int hrow = pr + 65 + dy*64 + dx;
                bH[g] = bbuf + hrow*128 + ((((uint32_t)hrow & 7) << 4) ^ lhi);
                bL[g] = bH[g] + B_LO;
            } else {
                bH[g] = sb32 + lhi;   // zero row
                bL[g] = bH[g];
            }
        }

#pragma unroll
        for (int s = 0; s < 4; ++s) {
            const uint32_t so = (uint32_t)(s << 5);
            uint32_t Ah[4][4], Al[4][4], Bh[2][4], Bl[2][4];
#pragma unroll
            for (int i = 0; i < 4; ++i) { LDSM4(Ah[i], aH[i] ^ so); LDSM4(Al[i], aL[i] ^ so); }
#pragma unroll
            for (int g = 0; g < 2; ++g) { LDSM4(Bh[g], bH[g] ^ so); LDSM4(Bl[g], bL[g] ^ so); }
#pragma unroll
            for (int i = 0; i < 4; ++i) {
#pragma unroll
                for (int j = 0; j < 4; ++j) {
                    const int g = j >> 1, o = j & 1;
                    MMA16816(c[i][j], Ah[i], Bh[g][o], Bh[g][o + 2]);
                    MMA16816(c[i][j], Ah[i], Bl[g][o], Bl[g][o + 2]);
                    MMA16816(c[i][j], Al[i], Bh[g][o], Bh[g][o + 2]);
                }
            }
        }
    }

    // ---------------- epilogue ----------------
    const float* nzrow = noise + (size_t)b*IMG;
    if (LAYER == 1) {
#pragma unroll
        for (int i = 0; i < 4; ++i) {
#pragma unroll
            for (int h = 0; h < 2; ++h) {
                const int co = co0 + wco*64 + i*16 + (lid >> 2) + h*8;
                const float dm  = __ldg(&dmod[b*256 + co]);
                const float nwv = __ldg(&nw[co]);
                float* orow = out + (size_t)(b*256 + co)*IMG;
#pragma unroll
                for (int j = 0; j < 4; ++j) {
                    const int px = px0 + wpx*32 + j*8 + (lid & 3)*2;
                    float v0 = dm*c[i][j][h*2 + 0] + nwv*__ldg(&nzrow[px]);
                    float v1 = dm*c[i][j][h*2 + 1] + nwv*__ldg(&nzrow[px + 1]);
                    v0 = (v0 > 0.f) ? v0 : 0.2f*v0;
                    v1 = (v1 > 0.f) ? v1 : 0.2f*v1;
                    *(float2*)(orow + px) = make_float2(v0, v1);
                }
            }
        }
    } else {
        __syncthreads();            // done reading A/B smem; reuse for transpose
        const int P = 272;          // bytes per px row (128 co * 2B + pad)
#pragma unroll
        for (int i = 0; i < 4; ++i) {
#pragma unroll
            for (int h = 0; h < 2; ++h) {
                const int col = wco*64 + i*16 + (lid >> 2) + h*8;  // co local
                const int co  = co0 + col;
                const float dm  = __ldg(&dmod[b*256 + co]);
                const float nwv = __ldg(&nw[co]);
                const float s2  = g_style2[b*256 + co];
#pragma unroll
                for (int j = 0; j < 4; ++j) {
                    const int pl = wpx*32 + j*8 + (lid & 3)*2;     // px local
                    float v0 = dm*c[i][j][h*2 + 0] + nwv*__ldg(&nzrow[px0 + pl]);
                    float v1 = dm*c[i][j][h*2 + 1] + nwv*__ldg(&nzrow[px0 + pl + 1]);
                    v0 = ((v0 > 0.f) ? v0 : 0.2f*v0) * s2;
                    v1 = ((v1 > 0.f) ? v1 : 0.2f*v1) * s2;
                    __nv_bfloat16 h0 = __float2bfloat16(v0);
                    __nv_bfloat16 h1 = __float2bfloat16(v1);
                    __nv_bfloat16 l0 = __float2bfloat16(v0 - __bfloat162float(h0));
                    __nv_bfloat16 l1 = __float2bfloat16(v1 - __bfloat162float(h1));
                    *(__nv_bfloat16*)(smem + pl*P + col*2)              = h0;
                    *(__nv_bfloat16*)(smem + (pl + 1)*P + col*2)        = h1;
                    *(__nv_bfloat16*)(smem + 34816 + pl*P + col*2)      = l0;
                    *(__nv_bfloat16*)(smem + 34816 + (pl + 1)*P + col*2)= l1;
                }
            }
        }
        __syncthreads();
        const int pl2 = tid >> 1, half = tid & 1;
        const uint4* srcH = (const uint4*)(smem + pl2*P + half*128);
        const uint4* srcL = (const uint4*)(smem + 34816 + pl2*P + half*128);
        size_t o = (size_t)(b*IMG + px0 + pl2)*256 + co0 + half*64;
        uint4* dh = (uint4*)(g_hh + o);
        uint4* dl = (uint4*)(g_hl + o);
#pragma unroll
        for (int j = 0; j < 8; ++j) { dh[j] = srcH[j]; dl[j] = srcL[j]; }
    }
}

// ---------------- launch ----------------
extern "C" void kernel_launch(void* const* d_in, const int* in_sizes, int n_in,
                              void* d_out, int out_size) {
    const float* x       = (const float*)d_in[0];
    const float* w1      = (const float*)d_in[1];
    const float* w2      = (const float*)d_in[2];
    const float* noise1  = (const float*)d_in[3];
    const float* noise2  = (const float*)d_in[4];
    const float* s1_w    = (const float*)d_in[5];
    const float* s1_b    = (const float*)d_in[6];
    const float* conv1_w = (const float*)d_in[7];
    const float* nw1     = (const float*)d_in[8];
    const float* s2_w    = (const float*)d_in[9];
    const float* s2_b    = (const float*)d_in[10];
    const float* conv2_w = (const float*)d_in[11];
    const float* nw2     = (const float*)d_in[12];
    float* out = (float*)d_out;

    cudaFuncSetAttribute(conv_hmma<0>, cudaFuncAttributeMaxDynamicSharedMemorySize, SMEM_TOTAL);
    cudaFuncSetAttribute(conv_hmma<1>, cudaFuncAttributeMaxDynamicSharedMemorySize, SMEM_TOTAL);

    style_kernel<0><<<16, 256>>>(w1, s1_w, s1_b);
    style_kernel<1><<<16, 256>>>(w2, s2_w, s2_b);
    wsq_kernel<0><<<256, 256>>>(conv1_w);
    wsq_kernel<1><<<256, 256>>>(conv2_w);
    demod_kernel<0><<<16, 256>>>();
    demod_kernel<1><<<16, 256>>>();
    wcv_kernel<0><<<2304, 256>>>(conv1_w);
    wcv_kernel<1><<<2304, 256>>>(conv2_w);
    xt_kernel<<<dim3(64, 4, 16), 256>>>(x);

    dim3 grid(32, 2, 16);  // px tiles (128px), co tiles (128co), batch
    conv_hmma<0><<<grid, 256, SMEM_TOTAL>>>(noise1, nw1, nullptr);
    conv_hmma<1><<<grid, 256, SMEM_TOTAL>>>(noise2, nw2, out);
}

// round 13
// speedup vs baseline: 1.7035x; 1.0006x over previous
#include <cuda_runtime.h>
#include <cuda_bf16.h>
#include <cstdint>

#define BB   16
#define CC   256
#define IMG  4096
#define KTOT 2304

// ---------------- device scratch ----------------
__device__ float g_style1[BB*CC], g_style2[BB*CC];
__device__ float g_demod1[BB*CC], g_demod2[BB*CC];
__device__ float g_wsq1[CC*CC],  g_wsq2[CC*CC];           // [ci][co] sum_t w^2
__device__ __nv_bfloat16 g_w1h[CC*KTOT], g_w1l[CC*KTOT];  // [co][tap*256+ci]
__device__ __nv_bfloat16 g_w2h[CC*KTOT], g_w2l[CC*KTOT];
__device__ __nv_bfloat16 g_xh[(size_t)BB*IMG*CC], g_xl[(size_t)BB*IMG*CC]; // [b][px][ci]
__device__ __nv_bfloat16 g_hh[(size_t)BB*IMG*CC], g_hl[(size_t)BB*IMG*CC];

// ---------------- helpers ----------------
__device__ __forceinline__ uint32_t smem_u32(const void* p) {
    uint32_t a;
    asm("{ .reg .u64 t; cvta.to.shared.u64 t, %1; cvt.u32.u64 %0, t; }" : "=r"(a) : "l"(p));
    return a;
}
__device__ __forceinline__ void cp16(uint32_t dst, const void* src) {
    asm volatile("cp.async.ca.shared.global [%0], [%1], 16;" :: "r"(dst), "l"(src) : "memory");
}
__device__ __forceinline__ void cp16z(uint32_t dst, const void* src, uint32_t sz) {
    asm volatile("cp.async.ca.shared.global [%0], [%1], 16, %2;" :: "r"(dst), "l"(src), "r"(sz) : "memory");
}
#define CP_WAIT_ALL() asm volatile("cp.async.wait_all;" ::: "memory")

#define LDSM4(r, a) \
    asm volatile("ldmatrix.sync.aligned.m8n8.x4.shared.b16 {%0,%1,%2,%3}, [%4];" \
        : "=r"((r)[0]), "=r"((r)[1]), "=r"((r)[2]), "=r"((r)[3]) : "r"(a))

#define MMA16816(c, a, b0, b1) \
    asm volatile("mma.sync.aligned.m16n8k16.row.col.f32.bf16.bf16.f32 " \
        "{%0,%1,%2,%3},{%4,%5,%6,%7},{%8,%9},{%0,%1,%2,%3};" \
        : "+f"((c)[0]), "+f"((c)[1]), "+f"((c)[2]), "+f"((c)[3]) \
        : "r"((a)[0]), "r"((a)[1]), "r"((a)[2]), "r"((a)[3]), "r"(b0), "r"(b1))

// ---------------- style = (w/32) @ s_w^T + s_b ----------------
template<int L>
__global__ void style_kernel(const float* __restrict__ wv, const float* __restrict__ sw,
                             const float* __restrict__ sb) {
    const int b = blockIdx.x, c = threadIdx.x;
    __shared__ float sv[512];
    sv[c] = wv[b*512 + c]; sv[c+256] = wv[b*512 + 256 + c];
    __syncthreads();
    float acc = 0.f;
    const float4* row = (const float4*)(sw + (size_t)c*512);
#pragma unroll 8
    for (int q = 0; q < 128; ++q) {
        float4 w4 = row[q];
        acc += w4.x*sv[4*q] + w4.y*sv[4*q+1] + w4.z*sv[4*q+2] + w4.w*sv[4*q+3];
    }
    (L == 0 ? g_style1 : g_style2)[b*256 + c] = acc * 0.03125f + sb[c];
}

// ---------------- wsq[ci][co] = sum_t w[co][ci][t]^2 ----------------
template<int L>
__global__ void wsq_kernel(const float* __restrict__ w) {
    int co = blockIdx.x, ci = threadIdx.x;
    const float* p = w + (size_t)co*KTOT + ci*9;
    float a = 0.f;
#pragma unroll
    for (int t = 0; t < 9; ++t) a += p[t]*p[t];
    (L == 0 ? g_wsq1 : g_wsq2)[ci*256 + co] = a;
}

// ---------------- demod ----------------
template<int L>
__global__ void demod_kernel() {
    const float* style = (L == 0) ? g_style1 : g_style2;
    const float* wsq   = (L == 0) ? g_wsq1   : g_wsq2;
    float*       dm    = (L == 0) ? g_demod1 : g_demod2;
    const int b = blockIdx.x, co = threadIdx.x;
    __shared__ float s2[256];
    float sv = style[b*256 + co];
    s2[co] = sv*sv;
    __syncthreads();
    float acc = 0.f;
    for (int ci = 0; ci < 256; ++ci) acc += s2[ci] * wsq[ci*256 + co];
    dm[b*256 + co] = rsqrtf(acc + 1e-8f);
}

// ---------------- weight convert: [co][ci*9+tap] -> bf16 hi/lo [co][tap*256+ci] ----
template<int L>
__global__ void wcv_kernel(const float* __restrict__ w) {
    int i = blockIdx.x*256 + threadIdx.x;
    int co = i / KTOT;
    int r  = i - co*KTOT;
    int tap = r >> 8, ci = r & 255;
    float v = w[(size_t)co*KTOT + ci*9 + tap];
    __nv_bfloat16 h = __float2bfloat16(v);
    (L == 0 ? g_w1h : g_w2h)[i] = h;
    (L == 0 ? g_w1l : g_w2l)[i] = __float2bfloat16(v - __bfloat162float(h));
}

// ---------------- x transpose + modulate + bf16 split -> [b][px][ci] ----------------
__global__ void xt_kernel(const float* __restrict__ x) {
    __shared__ float s[64][65];
    const int px0 = blockIdx.x << 6, ci0 = blockIdx.y << 6, b = blockIdx.z;
    const int t = threadIdx.x;
    for (int i = t; i < 1024; i += 256) {
        int ci = i >> 4, q = i & 15;
        float4 v = ((const float4*)(x + (size_t)(b*CC + ci0 + ci)*IMG + px0))[q];
        float st = g_style1[b*CC + ci0 + ci];
        s[ci][q*4+0] = v.x*st; s[ci][q*4+1] = v.y*st;
        s[ci][q*4+2] = v.z*st; s[ci][q*4+3] = v.w*st;
    }
    __syncthreads();
    const int px_l = t >> 2, seg = t & 3;
    __align__(16) __nv_bfloat16 hb[16], lb[16];
#pragma unroll
    for (int k = 0; k < 16; ++k) {
        float v = s[seg*16 + k][px_l];
        __nv_bfloat16 h = __float2bfloat16(v);
        hb[k] = h;
        lb[k] = __float2bfloat16(v - __bfloat162float(h));
    }
    size_t o = (size_t)(b*IMG + px0 + px_l)*256 + ci0 + seg*16;
    ((uint4*)(g_xh + o))[0] = ((const uint4*)hb)[0];
    ((uint4*)(g_xh + o))[1] = ((const uint4*)hb)[1];
    ((uint4*)(g_xl + o))[0] = ((const uint4*)lb)[0];
    ((uint4*)(g_xl + o))[1] = ((const uint4*)lb)[1];
}

// ================= HMMA implicit-GEMM conv3x3 + fused epilogue =================
// CTA: 128 co x 128 px, 8 warps (2 co-groups x 4 px-groups), warp tile 64x32.
// smem: [0,128)        zero row
//       [1024 +32K*ab) A stage: Ah 16K | Al 16K   (ab = it&1)
//       [66560+66K*bb) B halo : Bh 33792 | Bl 33792 (258 rows x 128B, bb = chunk&1)
#define A_OFF   1024
#define A_STG   32768
#define B_OFF   66560
#define B_STG   67584
#define B_LO    33792
#define SMEM_TOTAL (B_OFF + 2*B_STG)   // 201728

template<int LAYER>
__global__ void __launch_bounds__(256, 1)
conv_hmma(const float* __restrict__ noise, const float* __restrict__ nw,
          float* __restrict__ out) {
    extern __shared__ __align__(1024) char smem[];
    const uint32_t sb32 = smem_u32(smem);
    const int tid = threadIdx.x;
    const int lid = tid & 31, wid = tid >> 5;
    const int wco = wid & 1, wpx = wid >> 1;

    const int px0 = blockIdx.x << 7;
    const int co0 = blockIdx.y << 7;
    const int b   = blockIdx.z;

    const __nv_bfloat16* __restrict__ Bhp = (LAYER == 0) ? g_xh  : g_hh;
    const __nv_bfloat16* __restrict__ Blp = (LAYER == 0) ? g_xl  : g_hl;
    const __nv_bfloat16* __restrict__ Whp = (LAYER == 0) ? g_w1h : g_w2h;
    const __nv_bfloat16* __restrict__ Wlp = (LAYER == 0) ? g_w1l : g_w2l;
    const float* __restrict__ dmod = (LAYER == 0) ? g_demod1 : g_demod2;

    // zero row for invalid B lanes
    if (tid < 8) ((uint4*)smem)[tid] = make_uint4(0, 0, 0, 0);

    // ---- loaders ----
    auto loadA = [&](int it2) {
        const int ntap = it2 % 9, nci = (it2 / 9) << 6;
        const int co_l = tid >> 1, half = tid & 1;
        const size_t gs = (size_t)(co0 + co_l)*KTOT + ntap*256 + nci + half*32;
        const __nv_bfloat16* sh = Whp + gs;
        const __nv_bfloat16* sl = Wlp + gs;
        uint32_t d0 = sb32 + A_OFF + (it2 & 1)*A_STG
                    + co_l*128 + (((co_l & 7) << 4) ^ (half << 6));
#pragma unroll
        for (int j = 0; j < 4; ++j) {
            cp16(d0 ^ (j << 4),              sh + j*8);
            cp16((d0 + 16384) ^ (j << 4),    sl + j*8);
        }
    };
    auto loadB = [&](int chunk) {
        const uint32_t bb = sb32 + B_OFF + (chunk & 1)*B_STG;
        const int nci = chunk << 6;
        const int half = tid & 1;
        for (int r = tid >> 1; r < 258; r += 128) {
            int pp = px0 - 65 + r;
            bool ok = (pp >= 0) && (pp < IMG);
            int ppc = ok ? pp : 0;
            const size_t gs = ((size_t)(b*IMG + ppc))*256 + nci + half*32;
            const __nv_bfloat16* sh = Bhp + gs;
            const __nv_bfloat16* sl = Blp + gs;
            uint32_t sz = ok ? 16u : 0u;
            uint32_t d0 = bb + r*128 + (((r & 7) << 4) ^ (half << 6));
#pragma unroll
            for (int j = 0; j < 4; ++j) {
                cp16z(d0 ^ (j << 4),            sh + j*8, sz);
                cp16z((d0 + B_LO) ^ (j << 4),   sl + j*8, sz);
            }
        }
    };

    loadB(0);
    loadA(0);

    float c[4][4][4];
#pragma unroll
    for (int i = 0; i < 4; ++i)
#pragma unroll
        for (int j = 0; j < 4; ++j)
#pragma unroll
            for (int q = 0; q < 4; ++q) c[i][j][q] = 0.f;

    const int lrow = lid & 15;
    const uint32_t lhi = (uint32_t)((lid >> 4) << 4);

    for (int it = 0; it < 36; ++it) {
        CP_WAIT_ALL();
        __syncthreads();
        if (it + 1 < 36) {
            loadA(it + 1);
            if (((it + 1) % 9) == 0) loadB((it + 1) / 9);
        }

        const int chunk = it / 9;
        const int tap   = it - chunk*9;
        const int dy    = tap / 3 - 1;
        const int dx    = tap - (tap / 3)*3 - 1;
        const uint32_t abuf = sb32 + A_OFF + (it & 1)*A_STG;
        const uint32_t bbuf = sb32 + B_OFF + (chunk & 1)*B_STG;

        uint32_t aH[4], aL[4];
#pragma unroll
        for (int i = 0; i < 4; ++i) {
            int ar = wco*64 + i*16 + lrow;
            aH[i] = abuf + ar*128 + ((((uint32_t)ar & 7) << 4) ^ lhi);
            aL[i] = aH[i] + 16384;
        }
        uint32_t bH[2], bL[2];
#pragma unroll
        for (int g = 0; g < 2; ++g) {
            int pr = wpx*32 + g*16 + lrow;
            int x  = pr & 63;
            int pp = px0 + pr + dy*64 + dx;
            bool ok = !((x == 0 && dx < 0) || (x == 63 && dx > 0))
                      && (pp >= 0) && (pp < IMG);
            if (ok) {
                int hrow = pr + 65 + dy*64 + dx;
                bH[g] = bbuf + hrow*128 + ((((uint32_t)hrow & 7) << 4) ^ lhi);
                bL[g] = bH[g] + B_LO;
            } else {
                bH[g] = sb32 + lhi;   // zero row
                bL[g] = bH[g];
            }
        }

#pragma unroll
        for (int s = 0; s < 4; ++s) {
            const uint32_t so = (uint32_t)(s << 5);
            uint32_t Ah[4][4], Al[4][4], Bh[2][4], Bl[2][4];
#pragma unroll
            for (int i = 0; i < 4; ++i) { LDSM4(Ah[i], aH[i] ^ so); LDSM4(Al[i], aL[i] ^ so); }
#pragma unroll
            for (int g = 0; g < 2; ++g) { LDSM4(Bh[g], bH[g] ^ so); LDSM4(Bl[g], bL[g] ^ so); }
#pragma unroll
            for (int i = 0; i < 4; ++i) {
#pragma unroll
                for (int j = 0; j < 4; ++j) {
                    const int g = j >> 1, o = j & 1;
                    MMA16816(c[i][j], Ah[i], Bh[g][o], Bh[g][o + 2]);
                    MMA16816(c[i][j], Ah[i], Bl[g][o], Bl[g][o + 2]);
                    MMA16816(c[i][j], Al[i], Bh[g][o], Bh[g][o + 2]);
                }
            }
        }
    }

    // ---------------- epilogue ----------------
    const float* nzrow = noise + (size_t)b*IMG;
    if (LAYER == 1) {
#pragma unroll
        for (int i = 0; i < 4; ++i) {
#pragma unroll
            for (int h = 0; h < 2; ++h) {
                const int co = co0 + wco*64 + i*16 + (lid >> 2) + h*8;
                const float dm  = __ldg(&dmod[b*256 + co]);
                const float nwv = __ldg(&nw[co]);
                float* orow = out + (size_t)(b*256 + co)*IMG;
#pragma unroll
                for (int j = 0; j < 4; ++j) {
                    const int px = px0 + wpx*32 + j*8 + (lid & 3)*2;
                    float v0 = dm*c[i][j][h*2 + 0] + nwv*__ldg(&nzrow[px]);
                    float v1 = dm*c[i][j][h*2 + 1] + nwv*__ldg(&nzrow[px + 1]);
                    v0 = (v0 > 0.f) ? v0 : 0.2f*v0;
                    v1 = (v1 > 0.f) ? v1 : 0.2f*v1;
                    *(float2*)(orow + px) = make_float2(v0, v1);
                }
            }
        }
    } else {
        __syncthreads();            // done reading A/B smem; reuse for transpose
        const int P = 272;          // bytes per px row (128 co * 2B + pad)
#pragma unroll
        for (int i = 0; i < 4; ++i) {
#pragma unroll
            for (int h = 0; h < 2; ++h) {
                const int col = wco*64 + i*16 + (lid >> 2) + h*8;  // co local
                const int co  = co0 + col;
                const float dm  = __ldg(&dmod[b*256 + co]);
                const float nwv = __ldg(&nw[co]);
                const float s2  = g_style2[b*256 + co];
#pragma unroll
                for (int j = 0; j < 4; ++j) {
                    const int pl = wpx*32 + j*8 + (lid & 3)*2;     // px local
                    float v0 = dm*c[i][j][h*2 + 0] + nwv*__ldg(&nzrow[px0 + pl]);
                    float v1 = dm*c[i][j][h*2 + 1] + nwv*__ldg(&nzrow[px0 + pl + 1]);
                    v0 = ((v0 > 0.f) ? v0 : 0.2f*v0) * s2;
                    v1 = ((v1 > 0.f) ? v1 : 0.2f*v1) * s2;
                    __nv_bfloat16 h0 = __float2bfloat16(v0);
                    __nv_bfloat16 h1 = __float2bfloat16(v1);
                    __nv_bfloat16 l0 = __float2bfloat16(v0 - __bfloat162float(h0));
                    __nv_bfloat16 l1 = __float2bfloat16(v1 - __bfloat162float(h1));
                    *(__nv_bfloat16*)(smem + pl*P + col*2)              = h0;
                    *(__nv_bfloat16*)(smem + (pl + 1)*P + col*2)        = h1;
                    *(__nv_bfloat16*)(smem + 34816 + pl*P + col*2)      = l0;
                    *(__nv_bfloat16*)(smem + 34816 + (pl + 1)*P + col*2)= l1;
                }
            }
        }
        __syncthreads();
        const int pl2 = tid >> 1, half = tid & 1;
        const uint4* srcH = (const uint4*)(smem + pl2*P + half*128);
        const uint4* srcL = (const uint4*)(smem + 34816 + pl2*P + half*128);
        size_t o = (size_t)(b*IMG + px0 + pl2)*256 + co0 + half*64;
        uint4* dh = (uint4*)(g_hh + o);
        uint4* dl = (uint4*)(g_hl + o);
#pragma unroll
        for (int j = 0; j < 8; ++j) { dh[j] = srcH[j]; dl[j] = srcL[j]; }
    }
}

// ---------------- launch ----------------
extern "C" void kernel_launch(void* const* d_in, const int* in_sizes, int n_in,
                              void* d_out, int out_size) {
    const float* x       = (const float*)d_in[0];
    const float* w1      = (const float*)d_in[1];
    const float* w2      = (const float*)d_in[2];
    const float* noise1  = (const float*)d_in[3];
    const float* noise2  = (const float*)d_in[4];
    const float* s1_w    = (const float*)d_in[5];
    const float* s1_b    = (const float*)d_in[6];
    const float* conv1_w = (const float*)d_in[7];
    const float* nw1     = (const float*)d_in[8];
    const float* s2_w    = (const float*)d_in[9];
    const float* s2_b    = (const float*)d_in[10];
    const float* conv2_w = (const float*)d_in[11];
    const float* nw2     = (const float*)d_in[12];
    float* out = (float*)d_out;

    cudaFuncSetAttribute(conv_hmma<0>, cudaFuncAttributeMaxDynamicSharedMemorySize, SMEM_TOTAL);
    cudaFuncSetAttribute(conv_hmma<1>, cudaFuncAttributeMaxDynamicSharedMemorySize, SMEM_TOTAL);

    style_kernel<0><<<16, 256>>>(w1, s1_w, s1_b);
    style_kernel<1><<<16, 256>>>(w2, s2_w, s2_b);
    wsq_kernel<0><<<256, 256>>>(conv1_w);
    wsq_kernel<1><<<256, 256>>>(conv2_w);
    demod_kernel<0><<<16, 256>>>();
    demod_kernel<1><<<16, 256>>>();
    wcv_kernel<0><<<2304, 256>>>(conv1_w);
    wcv_kernel<1><<<2304, 256>>>(conv2_w);
    xt_kernel<<<dim3(64, 4, 16), 256>>>(x);

    dim3 grid(32, 2, 16);  // px tiles (128px), co tiles (128co), batch
    conv_hmma<0><<<grid, 256, SMEM_TOTAL>>>(noise1, nw1, nullptr);
    conv_hmma<1><<<grid, 256, SMEM_TOTAL>>>(noise2, nw2, out);
}

// round 14
// speedup vs baseline: 1.7070x; 1.0020x over previous
#include <cuda_runtime.h>
#include <cuda_bf16.h>
#include <cstdint>

#define BB   16
#define CC   256
#define IMG  4096
#define KTOT 2304

// ---------------- device scratch ----------------
__device__ float g_style1[BB*CC], g_style2[BB*CC];
__device__ float g_demod1[BB*CC], g_demod2[BB*CC];
__device__ float g_wsq1[CC*CC],  g_wsq2[CC*CC];           // [ci][co] sum_t w^2
__device__ __nv_bfloat16 g_w1h[CC*KTOT], g_w1l[CC*KTOT];  // [co][tap*256+ci]
__device__ __nv_bfloat16 g_w2h[CC*KTOT], g_w2l[CC*KTOT];
__device__ __nv_bfloat16 g_xh[(size_t)BB*IMG*CC], g_xl[(size_t)BB*IMG*CC]; // [b][px][ci]
__device__ __nv_bfloat16 g_hh[(size_t)BB*IMG*CC], g_hl[(size_t)BB*IMG*CC];

// ---------------- helpers ----------------
__device__ __forceinline__ uint32_t smem_u32(const void* p) {
    uint32_t a;
    asm("{ .reg .u64 t; cvta.to.shared.u64 t, %1; cvt.u32.u64 %0, t; }" : "=r"(a) : "l"(p));
    return a;
}
__device__ __forceinline__ void cp16(uint32_t dst, const void* src) {
    asm volatile("cp.async.ca.shared.global [%0], [%1], 16;" :: "r"(dst), "l"(src) : "memory");
}
__device__ __forceinline__ void cp16z(uint32_t dst, const void* src, uint32_t sz) {
    asm volatile("cp.async.ca.shared.global [%0], [%1], 16, %2;" :: "r"(dst), "l"(src), "r"(sz) : "memory");
}
#define CP_WAIT_ALL() asm volatile("cp.async.wait_all;" ::: "memory")

#define LDSM4(r, a) \
    asm volatile("ldmatrix.sync.aligned.m8n8.x4.shared.b16 {%0,%1,%2,%3}, [%4];" \
        : "=r"((r)[0]), "=r"((r)[1]), "=r"((r)[2]), "=r"((r)[3]) : "r"(a))

#define MMA16816(c, a, b0, b1) \
    asm volatile("mma.sync.aligned.m16n8k16.row.col.f32.bf16.bf16.f32 " \
        "{%0,%1,%2,%3},{%4,%5,%6,%7},{%8,%9},{%0,%1,%2,%3};" \
        : "+f"((c)[0]), "+f"((c)[1]), "+f"((c)[2]), "+f"((c)[3]) \
        : "r"((a)[0]), "r"((a)[1]), "r"((a)[2]), "r"((a)[3]), "r"(b0), "r"(b1))

// ---------------- style = (w/32) @ s_w^T + s_b ----------------
template<int L>
__global__ void style_kernel(const float* __restrict__ wv, const float* __restrict__ sw,
                             const float* __restrict__ sb) {
    const int b = blockIdx.x, c = threadIdx.x;
    __shared__ float sv[512];
    sv[c] = wv[b*512 + c]; sv[c+256] = wv[b*512 + 256 + c];
    __syncthreads();
    float acc = 0.f;
    const float4* row = (const float4*)(sw + (size_t)c*512);
#pragma unroll 8
    for (int q = 0; q < 128; ++q) {
        float4 w4 = row[q];
        acc += w4.x*sv[4*q] + w4.y*sv[4*q+1] + w4.z*sv[4*q+2] + w4.w*sv[4*q+3];
    }
    (L == 0 ? g_style1 : g_style2)[b*256 + c] = acc * 0.03125f + sb[c];
}

// ---------------- wsq[ci][co] = sum_t w[co][ci][t]^2 ----------------
template<int L>
__global__ void wsq_kernel(const float* __restrict__ w) {
    int co = blockIdx.x, ci = threadIdx.x;
    const float* p = w + (size_t)co*KTOT + ci*9;
    float a = 0.f;
#pragma unroll
    for (int t = 0; t < 9; ++t) a += p[t]*p[t];
    (L == 0 ? g_wsq1 : g_wsq2)[ci*256 + co] = a;
}

// ---------------- demod ----------------
template<int L>
__global__ void demod_kernel() {
    const float* style = (L == 0) ? g_style1 : g_style2;
    const float* wsq   = (L == 0) ? g_wsq1   : g_wsq2;
    float*       dm    = (L == 0) ? g_demod1 : g_demod2;
    const int b = blockIdx.x, co = threadIdx.x;
    __shared__ float s2[256];
    float sv = style[b*256 + co];
    s2[co] = sv*sv;
    __syncthreads();
    float acc = 0.f;
    for (int ci = 0; ci < 256; ++ci) acc += s2[ci] * wsq[ci*256 + co];
    dm[b*256 + co] = rsqrtf(acc + 1e-8f);
}

// ---------------- weight convert: [co][ci*9+tap] -> bf16 hi/lo [co][tap*256+ci] ----
template<int L>
__global__ void wcv_kernel(const float* __restrict__ w) {
    int i = blockIdx.x*256 + threadIdx.x;
    int co = i / KTOT;
    int r  = i - co*KTOT;
    int tap = r >> 8, ci = r & 255;
    float v = w[(size_t)co*KTOT + ci*9 + tap];
    __nv_bfloat16 h = __float2bfloat16(v);
    (L == 0 ? g_w1h : g_w2h)[i] = h;
    (L == 0 ? g_w1l : g_w2l)[i] = __float2bfloat16(v - __bfloat162float(h));
}

// ---------------- x transpose + modulate + bf16 split -> [b][px][ci] ----------------
__global__ void xt_kernel(const float* __restrict__ x) {
    __shared__ float s[64][65];
    const int px0 = blockIdx.x << 6, ci0 = blockIdx.y << 6, b = blockIdx.z;
    const int t = threadIdx.x;
    for (int i = t; i < 1024; i += 256) {
        int ci = i >> 4, q = i & 15;
        float4 v = ((const float4*)(x + (size_t)(b*CC + ci0 + ci)*IMG + px0))[q];
        float st = g_style1[b*CC + ci0 + ci];
        s[ci][q*4+0] = v.x*st; s[ci][q*4+1] = v.y*st;
        s[ci][q*4+2] = v.z*st; s[ci][q*4+3] = v.w*st;
    }
    __syncthreads();
    const int px_l = t >> 2, seg = t & 3;
    __align__(16) __nv_bfloat16 hb[16], lb[16];
#pragma unroll
    for (int k = 0; k < 16; ++k) {
        float v = s[seg*16 + k][px_l];
        __nv_bfloat16 h = __float2bfloat16(v);
        hb[k] = h;
        lb[k] = __float2bfloat16(v - __bfloat162float(h));
    }
    size_t o = (size_t)(b*IMG + px0 + px_l)*256 + ci0 + seg*16;
    ((uint4*)(g_xh + o))[0] = ((const uint4*)hb)[0];
    ((uint4*)(g_xh + o))[1] = ((const uint4*)hb)[1];
    ((uint4*)(g_xl + o))[0] = ((const uint4*)lb)[0];
    ((uint4*)(g_xl + o))[1] = ((const uint4*)lb)[1];
}

// ================= HMMA implicit-GEMM conv3x3 + fused epilogue =================
// CTA: 128 co x 128 px, 8 warps (2 co-groups x 4 px-groups), warp tile 64x32.
// smem: [0,128)        zero row
//       [1024 +32K*ab) A stage: Ah 16K | Al 16K   (ab = it&1)
//       [66560+66K*bb) B halo : Bh 33792 | Bl 33792 (258 rows x 128B, bb = chunk&1)
#define A_OFF   1024
#define A_STG   32768
#define B_OFF   66560
#define B_STG   67584
#define B_LO    33792
#define SMEM_TOTAL (B_OFF + 2*B_STG)   // 201728

template<int LAYER>
__global__ void __launch_bounds__(256, 1)
conv_hmma(const float* __restrict__ noise, const float* __restrict__ nw,
          float* __restrict__ out) {
    extern __shared__ __align__(1024) char smem[];
    const uint32_t sb32 = smem_u32(smem);
    const int tid = threadIdx.x;
    const int lid = tid & 31, wid = tid >> 5;
    const int wco = wid & 1, wpx = wid >> 1;

    const int px0 = blockIdx.x << 7;
    const int co0 = blockIdx.y << 7;
    const int b   = blockIdx.z;

    const __nv_bfloat16* __restrict__ Bhp = (LAYER == 0) ? g_xh  : g_hh;
    const __nv_bfloat16* __restrict__ Blp = (LAYER == 0) ? g_xl  : g_hl;
    const __nv_bfloat16* __restrict__ Whp = (LAYER == 0) ? g_w1h : g_w2h;
    const __nv_bfloat16* __restrict__ Wlp = (LAYER == 0) ? g_w1l : g_w2l;
    const float* __restrict__ dmod = (LAYER == 0) ? g_demod1 : g_demod2;

    // zero row for invalid B lanes
    if (tid < 8) ((uint4*)smem)[tid] = make_uint4(0, 0, 0, 0);

    // ---- loaders ----
    auto loadA = [&](int it2) {
        const int ntap = it2 % 9, nci = (it2 / 9) << 6;
        const int co_l = tid >> 1, half = tid & 1;
        const size_t gs = (size_t)(co0 + co_l)*KTOT + ntap*256 + nci + half*32;
        const __nv_bfloat16* sh = Whp + gs;
        const __nv_bfloat16* sl = Wlp + gs;
        uint32_t d0 = sb32 + A_OFF + (it2 & 1)*A_STG
                    + co_l*128 + (((co_l & 7) << 4) ^ (half << 6));
#pragma unroll
        for (int j = 0; j < 4; ++j) {
            cp16(d0 ^ (j << 4),              sh + j*8);
            cp16((d0 + 16384) ^ (j << 4),    sl + j*8);
        }
    };
    auto loadB = [&](int chunk) {
        const uint32_t bb = sb32 + B_OFF + (chunk & 1)*B_STG;
        const int nci = chunk << 6;
        const int half = tid & 1;
        for (int r = tid >> 1; r < 258; r += 128) {
            int pp = px0 - 65 + r;
            bool ok = (pp >= 0) && (pp < IMG);
            int ppc = ok ? pp : 0;
            const size_t gs = ((size_t)(b*IMG + ppc))*256 + nci + half*32;
            const __nv_bfloat16* sh = Bhp + gs;
            const __nv_bfloat16* sl = Blp + gs;
            uint32_t sz = ok ? 16u : 0u;
            uint32_t d0 = bb + r*128 + (((r & 7) << 4) ^ (half << 6));
#pragma unroll
            for (int j = 0; j < 4; ++j) {
                cp16z(d0 ^ (j << 4),            sh + j*8, sz);
                cp16z((d0 + B_LO) ^ (j << 4),   sl + j*8, sz);
            }
        }
    };

    loadB(0);
    loadA(0);

    float c[4][4][4];
#pragma unroll
    for (int i = 0; i < 4; ++i)
#pragma unroll
        for (int j = 0; j < 4; ++j)
#pragma unroll
            for (int q = 0; q < 4; ++q) c[i][j][q] = 0.f;

    const int lrow = lid & 15;
    const uint32_t lhi = (uint32_t)((lid >> 4) << 4);

    for (int it = 0; it < 36; ++it) {
        CP_WAIT_ALL();
        __syncthreads();
        if (it + 1 < 36) {
            loadA(it + 1);
            if (((it + 1) % 9) == 0) loadB((it + 1) / 9);
        }

        const int chunk = it / 9;
        const int tap   = it - chunk*9;
        const int dy    = tap / 3 - 1;
        const int dx    = tap - (tap / 3)*3 - 1;
        const uint32_t abuf = sb32 + A_OFF + (it & 1)*A_STG;
        const uint32_t bbuf = sb32 + B_OFF + (chunk & 1)*B_STG;

        uint32_t aH[4], aL[4];
#pragma unroll
        for (int i = 0; i < 4; ++i) {
            int ar = wco*64 + i*16 + lrow;
            aH[i] = abuf + ar*128 + ((((uint32_t)ar & 7) << 4) ^ lhi);
            aL[i] = aH[i] + 16384;
        }
        uint32_t bH[2], bL[2];
#pragma unroll
        for (int g = 0; g < 2; ++g) {
            int pr = wpx*32 + g*16 + lrow;
            int x  = pr & 63;
            int pp = px0 + pr + dy*64 + dx;
            bool ok = !((x == 0 && dx < 0) || (x == 63 && dx > 0))
                      && (pp >= 0) && (pp < IMG);
            if (ok) {
                int hrow = pr + 65 + dy*64 + dx;
                bH[g] = bbuf + hrow*128 + ((((uint32_t)hrow & 7) << 4) ^ lhi);
                bL[g] = bH[g] + B_LO;
            } else {
                bH[g] = sb32 + lhi;   // zero row
                bL[g] = bH[g];
            }
        }

#pragma unroll
        for (int s = 0; s < 4; ++s) {
            const uint32_t so = (uint32_t)(s << 5);
            uint32_t Ah[4][4], Al[4][4], Bh[2][4], Bl[2][4];
#pragma unroll
            for (int i = 0; i < 4; ++i) { LDSM4(Ah[i], aH[i] ^ so); LDSM4(Al[i], aL[i] ^ so); }
#pragma unroll
            for (int g = 0; g < 2; ++g) { LDSM4(Bh[g], bH[g] ^ so); LDSM4(Bl[g], bL[g] ^ so); }
#pragma unroll
            for (int i = 0; i < 4; ++i) {
#pragma unroll
                for (int j = 0; j < 4; ++j) {
                    const int g = j >> 1, o = j & 1;
                    MMA16816(c[i][j], Ah[i], Bh[g][o], Bh[g][o + 2]);
                    MMA16816(c[i][j], Ah[i], Bl[g][o], Bl[g][o + 2]);
                    MMA16816(c[i][j], Al[i], Bh[g][o], Bh[g][o + 2]);
                }
            }
        }
    }

    // ---------------- epilogue ----------------
    const float* nzrow = noise + (size_t)b*IMG;
    if (LAYER == 1) {
#pragma unroll
        for (int i = 0; i < 4; ++i) {
#pragma unroll
            for (int h = 0; h < 2; ++h) {
                const int co = co0 + wco*64 + i*16 + (lid >> 2) + h*8;
                const float dm  = __ldg(&dmod[b*256 + co]);
                const float nwv = __ldg(&nw[co]);
                float* orow = out + (size_t)(b*256 + co)*IMG;
#pragma unroll
                for (int j = 0; j < 4; ++j) {
                    const int px = px0 + wpx*32 + j*8 + (lid & 3)*2;
                    float v0 = dm*c[i][j][h*2 + 0] + nwv*__ldg(&nzrow[px]);
                    float v1 = dm*c[i][j][h*2 + 1] + nwv*__ldg(&nzrow[px + 1]);
                    v0 = (v0 > 0.f) ? v0 : 0.2f*v0;
                    v1 = (v1 > 0.f) ? v1 : 0.2f*v1;
                    *(float2*)(orow + px) = make_float2(v0, v1);
                }
            }
        }
    } else {
        __syncthreads();            // done reading A/B smem; reuse for transpose
        const int P = 272;          // bytes per px row (128 co * 2B + pad)
#pragma unroll
        for (int i = 0; i < 4; ++i) {
#pragma unroll
            for (int h = 0; h < 2; ++h) {
                const int col = wco*64 + i*16 + (lid >> 2) + h*8;  // co local
                const int co  = co0 + col;
                const float dm  = __ldg(&dmod[b*256 + co]);
                const float nwv = __ldg(&nw[co]);
                const float s2  = g_style2[b*256 + co];
#pragma unroll
                for (int j = 0; j < 4; ++j) {
                    const int pl = wpx*32 + j*8 + (lid & 3)*2;     // px local
                    float v0 = dm*c[i][j][h*2 + 0] + nwv*__ldg(&nzrow[px0 + pl]);
                    float v1 = dm*c[i][j][h*2 + 1] + nwv*__ldg(&nzrow[px0 + pl + 1]);
                    v0 = ((v0 > 0.f) ? v0 : 0.2f*v0) * s2;
                    v1 = ((v1 > 0.f) ? v1 : 0.2f*v1) * s2;
                    __nv_bfloat16 h0 = __float2bfloat16(v0);
                    __nv_bfloat16 h1 = __float2bfloat16(v1);
                    __nv_bfloat16 l0 = __float2bfloat16(v0 - __bfloat162float(h0));
                    __nv_bfloat16 l1 = __float2bfloat16(v1 - __bfloat162float(h1));
                    *(__nv_bfloat16*)(smem + pl*P + col*2)              = h0;
                    *(__nv_bfloat16*)(smem + (pl + 1)*P + col*2)        = h1;
                    *(__nv_bfloat16*)(smem + 34816 + pl*P + col*2)      = l0;
                    *(__nv_bfloat16*)(smem + 34816 + (pl + 1)*P + col*2)= l1;
                }
            }
        }
        __syncthreads();
        const int pl2 = tid >> 1, half = tid & 1;
        const uint4* srcH = (const uint4*)(smem + pl2*P + half*128);
        const uint4* srcL = (const uint4*)(smem + 34816 + pl2*P + half*128);
        size_t o = (size_t)(b*IMG + px0 + pl2)*256 + co0 + half*64;
        uint4* dh = (uint4*)(g_hh + o);
        uint4* dl = (uint4*)(g_hl + o);
#pragma unroll
        for (int j = 0; j < 8; ++j) { dh[j] = srcH[j]; dl[j] = srcL[j]; }
    }
}

// ---------------- launch ----------------
extern "C" void kernel_launch(void* const* d_in, const int* in_sizes, int n_in,
                              void* d_out, int out_size) {
    const float* x       = (const float*)d_in[0];
    const float* w1      = (const float*)d_in[1];
    const float* w2      = (const float*)d_in[2];
    const float* noise1  = (const float*)d_in[3];
    const float* noise2  = (const float*)d_in[4];
    const float* s1_w    = (const float*)d_in[5];
    const float* s1_b    = (const float*)d_in[6];
    const float* conv1_w = (const float*)d_in[7];
    const float* nw1     = (const float*)d_in[8];
    const float* s2_w    = (const float*)d_in[9];
    const float* s2_b    = (const float*)d_in[10];
    const float* conv2_w = (const float*)d_in[11];
    const float* nw2     = (const float*)d_in[12];
    float* out = (float*)d_out;

    cudaFuncSetAttribute(conv_hmma<0>, cudaFuncAttributeMaxDynamicSharedMemorySize, SMEM_TOTAL);
    cudaFuncSetAttribute(conv_hmma<1>, cudaFuncAttributeMaxDynamicSharedMemorySize, SMEM_TOTAL);

    style_kernel<0><<<16, 256>>>(w1, s1_w, s1_b);
    style_kernel<1><<<16, 256>>>(w2, s2_w, s2_b);
    wsq_kernel<0><<<256, 256>>>(conv1_w);
    wsq_kernel<1><<<256, 256>>>(conv2_w);
    demod_kernel<0><<<16, 256>>>();
    demod_kernel<1><<<16, 256>>>();
    wcv_kernel<0><<<2304, 256>>>(conv1_w);
    wcv_kernel<1><<<2304, 256>>>(conv2_w);
    xt_kernel<<<dim3(64, 4, 16), 256>>>(x);

    dim3 grid(32, 2, 16);  // px tiles (128px), co tiles (128co), batch
    conv_hmma<0><<<grid, 256, SMEM_TOTAL>>>(noise1, nw1, nullptr);
    conv_hmma<1><<<grid, 256, SMEM_TOTAL>>>(noise2, nw2, out);
}